// round 11
// baseline (speedup 1.0000x reference)
#include <cuda_runtime.h>
#include <cstdint>
#include <math.h>

// SimRel via single-pass fp16 mma.sync. R11 = R10 + full software pipelining
// of BOTH 4-row LDG waves: wave0(t+1) issued before MMA(t), wave1(t+1) issued
// between MMA(t) and the epilogue (s-regs dead there). Removes the ~300cyc
// exposed DRAM stall R10 had on wave1 at the top of each tile.
// 256 thr x 3 CTAs/SM, tile M=64, warp tile 16 rows x 32 classes.
// out = dot * rsqrt(|x|^2) * rsqrt(|a|^2) (norms exact fp32); 1.0 on inf rows.
// B=262144, D=256, C=64.

#define THREADS 256
#define SROW    528                 // 264 fp16 per row (256 + 8 pad), bytes

// ---- smem layout (bytes) ----
#define S_A     0                   // [64 x 264] fp16 centroids     33792
#define S_X     33792               // [64 x 264] fp16 X tile        33792
#define S_XINV  67584               // [64] f32 row rsqrt norms        256
#define S_CNI   67840               // [64] f32 centroid rsqrt norms   256
#define S_INF   68096               // [64] int inf flags              256
#define S_TOTAL 68352               // x3 CTAs = 205KB <= 228KB/SM

__device__ __forceinline__ void sts64(uint32_t a, uint32_t x, uint32_t y) {
    asm volatile("st.shared.v2.b32 [%0], {%1,%2};" :: "r"(a), "r"(x), "r"(y));
}
__device__ __forceinline__ void ldsm4(uint32_t a, uint32_t& r0, uint32_t& r1,
                                      uint32_t& r2, uint32_t& r3) {
    asm volatile("ldmatrix.sync.aligned.m8n8.x4.shared.b16 {%0,%1,%2,%3}, [%4];"
                 : "=r"(r0), "=r"(r1), "=r"(r2), "=r"(r3) : "r"(a));
}
__device__ __forceinline__ void mma16816(float* c, uint32_t a0, uint32_t a1,
                                         uint32_t a2, uint32_t a3,
                                         uint32_t b0, uint32_t b1) {
    asm volatile("mma.sync.aligned.m16n8k16.row.col.f32.f16.f16.f32 "
                 "{%0,%1,%2,%3}, {%4,%5,%6,%7}, {%8,%9}, {%0,%1,%2,%3};"
                 : "+f"(c[0]), "+f"(c[1]), "+f"(c[2]), "+f"(c[3])
                 : "r"(a0), "r"(a1), "r"(a2), "r"(a3), "r"(b0), "r"(b1));
}
__device__ __forceinline__ void cvt_f16(float4 v, uint32_t& r0, uint32_t& r1) {
    asm("cvt.rn.f16x2.f32 %0, %1, %2;" : "=r"(r0) : "f"(v.y), "f"(v.x));
    asm("cvt.rn.f16x2.f32 %0, %1, %2;" : "=r"(r1) : "f"(v.w), "f"(v.z));
}
__device__ __forceinline__ void stg_cs64(float* p, float2 v) {
    asm volatile("st.global.cs.v2.f32 [%0], {%1,%2};" :: "l"(p), "f"(v.x), "f"(v.y));
}
__device__ __forceinline__ float sum8(float4 a, float4 b) {
    float s = a.x * a.x;
    s = fmaf(a.y, a.y, s); s = fmaf(a.z, a.z, s); s = fmaf(a.w, a.w, s);
    s = fmaf(b.x, b.x, s); s = fmaf(b.y, b.y, s);
    s = fmaf(b.z, b.z, s); s = fmaf(b.w, b.w, s);
    return s;
}

__global__ void __launch_bounds__(THREADS, 3)
SimRel_48335561949951_kernel(const float* __restrict__ X,
                             const float* __restrict__ A,
                             float* __restrict__ out,
                             int B, int ntiles) {
    extern __shared__ char smem[];
    const uint32_t sb = (uint32_t)__cvta_generic_to_shared(smem);
    float* xinv_s = (float*)(smem + S_XINV);
    float* cni_s  = (float*)(smem + S_CNI);
    int*   inf_s  = (int*)(smem + S_INF);

    const int tid = threadIdx.x, w = tid >> 5, l = tid & 31;
    const int q = w >> 1;           // M-slot: rows q*16..q*16+15
    const int h = w & 1;            // N-slot: classes h*32..h*32+31

    // ---- centroid conversion + norms + inf flags (8 rows per warp, once) ----
    #pragma unroll
    for (int rr = 0; rr < 8; rr++) {
        int r = w * 8 + rr;
        const float4* pa = (const float4*)(A + (size_t)r * 256);
        float4 v0 = pa[l], v1 = pa[32 + l];
        uint32_t c0r, c1r;
        cvt_f16(v0, c0r, c1r);
        sts64(sb + S_A + r * SROW + 8 * l, c0r, c1r);
        cvt_f16(v1, c0r, c1r);
        sts64(sb + S_A + r * SROW + 256 + 8 * l, c0r, c1r);
        float ss = sum8(v0, v1);
        int bad = (fabsf(v0.x) == INFINITY) | (fabsf(v0.y) == INFINITY) |
                  (fabsf(v0.z) == INFINITY) | (fabsf(v0.w) == INFINITY) |
                  (fabsf(v1.x) == INFINITY) | (fabsf(v1.y) == INFINITY) |
                  (fabsf(v1.z) == INFINITY) | (fabsf(v1.w) == INFINITY);
        #pragma unroll
        for (int o = 16; o; o >>= 1) ss += __shfl_xor_sync(0xffffffffu, ss, o);
        unsigned m = __ballot_sync(0xffffffffu, bad);
        if (l == 0) { cni_s[r] = rsqrtf(ss); inf_s[r] = (m != 0); }
    }
    __syncthreads();

    // ---- per-lane ldmatrix fragment offsets ----
    const int t8 = l >> 3;
    const uint32_t frag_off = (uint32_t)(((t8 & 1) * 8 + (l & 7)) * SROW + (t8 >> 1) * 16);
    const uint32_t xf  = sb + S_X + (uint32_t)(q * 16) * SROW + frag_off;   // 16 rows
    const uint32_t af0 = sb + S_A + (uint32_t)(h * 32) * SROW + frag_off;   // cls +0..15
    const uint32_t af1 = af0 + 16 * SROW;                                    // cls +16..31

    const int rbase = w * 8;        // 8 rows this warp loads (2 waves of 4)
    const int qr = l >> 2, qc = (l & 3) * 2;

    // ---- prologue: LDG both waves of the first tile ----
    float4 p0[4], p1[4];            // wave0 rows rbase..+3 (k 0-127 / 128-255)
    float4 s0[4], s1[4];            // wave1 rows rbase+4..+7
    {
        long long tb = (long long)blockIdx.x * 64;
        #pragma unroll
        for (int rr = 0; rr < 4; rr++) {
            long long gr = tb + rbase + rr; if (gr >= B) gr = B - 1;
            const float4* px = (const float4*)(X + gr * 256);
            p0[rr] = __ldcs(px + l);
            p1[rr] = __ldcs(px + 32 + l);
        }
        #pragma unroll
        for (int rr = 0; rr < 4; rr++) {
            long long gr = tb + rbase + 4 + rr; if (gr >= B) gr = B - 1;
            const float4* px = (const float4*)(X + gr * 256);
            s0[rr] = __ldcs(px + l);
            s1[rr] = __ldcs(px + 32 + l);
        }
    }

    for (int tile = blockIdx.x; tile < ntiles; tile += gridDim.x) {
        const long long tb = (long long)tile * 64;
        const uint32_t xsh = sb + S_X + (uint32_t)rbase * SROW;

        // convert wave0 -> fp16 smem + norms
        #pragma unroll
        for (int rr = 0; rr < 4; rr++) {
            uint32_t c0r, c1r;
            cvt_f16(p0[rr], c0r, c1r);
            sts64(xsh + rr * SROW + 8 * l, c0r, c1r);
            cvt_f16(p1[rr], c0r, c1r);
            sts64(xsh + rr * SROW + 256 + 8 * l, c0r, c1r);
            float ss = sum8(p0[rr], p1[rr]);
            #pragma unroll
            for (int o = 16; o; o >>= 1) ss += __shfl_xor_sync(0xffffffffu, ss, o);
            if (l == 0) xinv_s[rbase + rr] = rsqrtf(ss);
        }
        // convert wave1
        #pragma unroll
        for (int rr = 0; rr < 4; rr++) {
            uint32_t c0r, c1r;
            cvt_f16(s0[rr], c0r, c1r);
            sts64(xsh + (4 + rr) * SROW + 8 * l, c0r, c1r);
            cvt_f16(s1[rr], c0r, c1r);
            sts64(xsh + (4 + rr) * SROW + 256 + 8 * l, c0r, c1r);
            float ss = sum8(s0[rr], s1[rr]);
            #pragma unroll
            for (int o = 16; o; o >>= 1) ss += __shfl_xor_sync(0xffffffffu, ss, o);
            if (l == 0) xinv_s[rbase + 4 + rr] = rsqrtf(ss);
        }
        __syncthreads();   // X tile + norms complete; MMA(t-1) reads done

        const int nt = tile + gridDim.x;
        const long long nb = (long long)nt * 64;

        // prefetch wave0 of next tile (latency covered by MMA below)
        if (nt < ntiles) {
            #pragma unroll
            for (int rr = 0; rr < 4; rr++) {
                long long gr = nb + rbase + rr; if (gr >= B) gr = B - 1;
                const float4* px = (const float4*)(X + gr * 256);
                p0[rr] = __ldcs(px + l);
                p1[rr] = __ldcs(px + 32 + l);
            }
        }

        // MMA: 16 k-steps; warp computes 16 rows x 32 classes
        float acc[4][4];
        #pragma unroll
        for (int n = 0; n < 4; n++)
            #pragma unroll
            for (int j = 0; j < 4; j++) acc[n][j] = 0.0f;

        #pragma unroll
        for (int s = 0; s < 16; s++) {
            uint32_t a0, a1, a2, a3, b0, b1, b2, b3, c0, c1, c2, c3;
            ldsm4(xf + s * 32, a0, a1, a2, a3);
            ldsm4(af0 + s * 32, b0, b1, b2, b3);
            ldsm4(af1 + s * 32, c0, c1, c2, c3);
            mma16816(acc[0], a0, a1, a2, a3, b0, b2);
            mma16816(acc[1], a0, a1, a2, a3, b1, b3);
            mma16816(acc[2], a0, a1, a2, a3, c0, c2);
            mma16816(acc[3], a0, a1, a2, a3, c1, c3);
        }

        // prefetch wave1 of next tile (s-regs dead since convert; latency
        // covered by epilogue + closing sync + next convert-wave0)
        if (nt < ntiles) {
            #pragma unroll
            for (int rr = 0; rr < 4; rr++) {
                long long gr = nb + rbase + 4 + rr; if (gr >= B) gr = B - 1;
                const float4* px = (const float4*)(X + gr * 256);
                s0[rr] = __ldcs(px + l);
                s1[rr] = __ldcs(px + 32 + l);
            }
        }

        // epilogue — scale + streaming store (16 rows x 32 classes per warp)
        {
            int rloc = q * 16 + qr;
            float xi0 = xinv_s[rloc];
            float xi1 = xinv_s[rloc + 8];
            long long r0g = tb + rloc;
            float* o0 = out + r0g * 64;
            float* o1 = o0 + 8 * 64;
            #pragma unroll
            for (int n = 0; n < 4; n++) {
                int c0 = h * 32 + n * 8 + qc;
                float2 cn2 = *(const float2*)(cni_s + c0);
                int2   ff  = *(const int2*)(inf_s + c0);
                float2 v0, v1;
                v0.x = ff.x ? 1.0f : acc[n][0] * xi0 * cn2.x;
                v0.y = ff.y ? 1.0f : acc[n][1] * xi0 * cn2.y;
                v1.x = ff.x ? 1.0f : acc[n][2] * xi1 * cn2.x;
                v1.y = ff.y ? 1.0f : acc[n][3] * xi1 * cn2.y;
                if (r0g < B)     stg_cs64(o0 + c0, v0);
                if (r0g + 8 < B) stg_cs64(o1 + c0, v1);
            }
        }
        __syncthreads();   // all ldsm reads done before next tile's STS (WAR)
    }
}

extern "C" void kernel_launch(void* const* d_in, const int* in_sizes, int n_in,
                              void* d_out, int out_size) {
    const float* X = (const float*)d_in[0];   // inputs [B, 256] fp32
    // d_in[1] = labels (unused)
    const float* A = (const float*)d_in[2];   // class_avgs [64, 256] fp32
    float* out = (float*)d_out;

    int B = in_sizes[0] / 256;
    int ntiles = (B + 63) / 64;

    int dev = 0, nsm = 148;
    cudaGetDevice(&dev);
    cudaDeviceGetAttribute(&nsm, cudaDevAttrMultiProcessorCount, dev);

    int grid = 3 * nsm;             // 3 CTAs/SM, 24 warps/SM
    if (grid > ntiles) grid = ntiles;

    cudaFuncSetAttribute(SimRel_48335561949951_kernel,
                         cudaFuncAttributeMaxDynamicSharedMemorySize, S_TOTAL);

    SimRel_48335561949951_kernel<<<grid, THREADS, S_TOTAL>>>(X, A, out, B, ntiles);
}

// round 12
// speedup vs baseline: 1.2543x; 1.2543x over previous
#include <cuda_runtime.h>
#include <cstdint>
#include <math.h>

// SimRel via single-pass fp16 mma.sync. R12 = R10 + pair-decoupled barriers:
// X slice q (rows q*16..+15) is written AND ldsm-read only by warps {2q,2q+1},
// so both per-tile __syncthreads become bar.sync(q+1, 64) pair barriers ->
// 4 independent pair pipelines per CTA x 3 CTAs = 12 streams per SM.
// 256 thr x 3 CTAs/SM, tile M=64, warp tile 16 rows x 32 classes.
// out = dot * rsqrt(|x|^2) * rsqrt(|a|^2) (norms exact fp32); 1.0 on inf rows.
// B=262144, D=256, C=64.

#define THREADS 256
#define SROW    528                 // 264 fp16 per row (256 + 8 pad), bytes

// ---- smem layout (bytes) ----
#define S_A     0                   // [64 x 264] fp16 centroids     33792
#define S_X     33792               // [64 x 264] fp16 X tile        33792
#define S_XINV  67584               // [64] f32 row rsqrt norms        256
#define S_CNI   67840               // [64] f32 centroid rsqrt norms   256
#define S_INF   68096               // [64] int inf flags              256
#define S_TOTAL 68352               // x3 CTAs = 205KB <= 228KB/SM

__device__ __forceinline__ void sts64(uint32_t a, uint32_t x, uint32_t y) {
    asm volatile("st.shared.v2.b32 [%0], {%1,%2};" :: "r"(a), "r"(x), "r"(y));
}
__device__ __forceinline__ void ldsm4(uint32_t a, uint32_t& r0, uint32_t& r1,
                                      uint32_t& r2, uint32_t& r3) {
    asm volatile("ldmatrix.sync.aligned.m8n8.x4.shared.b16 {%0,%1,%2,%3}, [%4];"
                 : "=r"(r0), "=r"(r1), "=r"(r2), "=r"(r3) : "r"(a));
}
__device__ __forceinline__ void mma16816(float* c, uint32_t a0, uint32_t a1,
                                         uint32_t a2, uint32_t a3,
                                         uint32_t b0, uint32_t b1) {
    asm volatile("mma.sync.aligned.m16n8k16.row.col.f32.f16.f16.f32 "
                 "{%0,%1,%2,%3}, {%4,%5,%6,%7}, {%8,%9}, {%0,%1,%2,%3};"
                 : "+f"(c[0]), "+f"(c[1]), "+f"(c[2]), "+f"(c[3])
                 : "r"(a0), "r"(a1), "r"(a2), "r"(a3), "r"(b0), "r"(b1));
}
__device__ __forceinline__ void cvt_f16(float4 v, uint32_t& r0, uint32_t& r1) {
    asm("cvt.rn.f16x2.f32 %0, %1, %2;" : "=r"(r0) : "f"(v.y), "f"(v.x));
    asm("cvt.rn.f16x2.f32 %0, %1, %2;" : "=r"(r1) : "f"(v.w), "f"(v.z));
}
__device__ __forceinline__ void stg_cs64(float* p, float2 v) {
    asm volatile("st.global.cs.v2.f32 [%0], {%1,%2};" :: "l"(p), "f"(v.x), "f"(v.y));
}
__device__ __forceinline__ float sum8(float4 a, float4 b) {
    float s = a.x * a.x;
    s = fmaf(a.y, a.y, s); s = fmaf(a.z, a.z, s); s = fmaf(a.w, a.w, s);
    s = fmaf(b.x, b.x, s); s = fmaf(b.y, b.y, s);
    s = fmaf(b.z, b.z, s); s = fmaf(b.w, b.w, s);
    return s;
}

__global__ void __launch_bounds__(THREADS, 3)
SimRel_48335561949951_kernel(const float* __restrict__ X,
                             const float* __restrict__ A,
                             float* __restrict__ out,
                             int B, int ntiles) {
    extern __shared__ char smem[];
    const uint32_t sb = (uint32_t)__cvta_generic_to_shared(smem);
    float* xinv_s = (float*)(smem + S_XINV);
    float* cni_s  = (float*)(smem + S_CNI);
    int*   inf_s  = (int*)(smem + S_INF);

    const int tid = threadIdx.x, w = tid >> 5, l = tid & 31;
    const int q = w >> 1;           // pair id / M-slot: rows q*16..q*16+15
    const int h = w & 1;            // N-slot: classes h*32..h*32+31
    const int barid = q + 1;        // named barrier per pair (1..4)

    // ---- centroid conversion + norms + inf flags (8 rows per warp, once) ----
    #pragma unroll
    for (int rr = 0; rr < 8; rr++) {
        int r = w * 8 + rr;
        const float4* pa = (const float4*)(A + (size_t)r * 256);
        float4 v0 = pa[l], v1 = pa[32 + l];
        uint32_t c0r, c1r;
        cvt_f16(v0, c0r, c1r);
        sts64(sb + S_A + r * SROW + 8 * l, c0r, c1r);
        cvt_f16(v1, c0r, c1r);
        sts64(sb + S_A + r * SROW + 256 + 8 * l, c0r, c1r);
        float ss = sum8(v0, v1);
        int bad = (fabsf(v0.x) == INFINITY) | (fabsf(v0.y) == INFINITY) |
                  (fabsf(v0.z) == INFINITY) | (fabsf(v0.w) == INFINITY) |
                  (fabsf(v1.x) == INFINITY) | (fabsf(v1.y) == INFINITY) |
                  (fabsf(v1.z) == INFINITY) | (fabsf(v1.w) == INFINITY);
        #pragma unroll
        for (int o = 16; o; o >>= 1) ss += __shfl_xor_sync(0xffffffffu, ss, o);
        unsigned m = __ballot_sync(0xffffffffu, bad);
        if (l == 0) { cni_s[r] = rsqrtf(ss); inf_s[r] = (m != 0); }
    }
    __syncthreads();   // A tile + cni/inf visible to ALL warps (read-only after)

    // ---- per-lane ldmatrix fragment offsets ----
    const int t8 = l >> 3;
    const uint32_t frag_off = (uint32_t)(((t8 & 1) * 8 + (l & 7)) * SROW + (t8 >> 1) * 16);
    const uint32_t xf  = sb + S_X + (uint32_t)(q * 16) * SROW + frag_off;   // own 16 rows
    const uint32_t af0 = sb + S_A + (uint32_t)(h * 32) * SROW + frag_off;   // cls +0..15
    const uint32_t af1 = af0 + 16 * SROW;                                    // cls +16..31

    const int rbase = w * 8;        // 8 rows this warp loads (2 waves of 4)
    const int qr = l >> 2, qc = (l & 3) * 2;

    // ---- prologue: LDG wave0 (rows rbase..rbase+3) of first tile ----
    float4 p0[4], p1[4];            // wave0: k 0-127 / k 128-255
    {
        long long tb = (long long)blockIdx.x * 64;
        #pragma unroll
        for (int rr = 0; rr < 4; rr++) {
            long long gr = tb + rbase + rr; if (gr >= B) gr = B - 1;
            const float4* px = (const float4*)(X + gr * 256);
            p0[rr] = __ldcs(px + l);
            p1[rr] = __ldcs(px + 32 + l);
        }
    }

    for (int tile = blockIdx.x; tile < ntiles; tile += gridDim.x) {
        const long long tb = (long long)tile * 64;
        const uint32_t xsh = sb + S_X + (uint32_t)rbase * SROW;

        // LDG wave1 first (rows rbase+4..+7) so its latency is covered by
        // wave0's convert below. (acc regs are dead here -> 64 live regs OK.)
        float4 s0[4], s1[4];
        #pragma unroll
        for (int rr = 0; rr < 4; rr++) {
            long long gr = tb + rbase + 4 + rr; if (gr >= B) gr = B - 1;
            const float4* px = (const float4*)(X + gr * 256);
            s0[rr] = __ldcs(px + l);
            s1[rr] = __ldcs(px + 32 + l);
        }

        // convert wave0 -> fp16 smem + norms
        #pragma unroll
        for (int rr = 0; rr < 4; rr++) {
            uint32_t c0r, c1r;
            cvt_f16(p0[rr], c0r, c1r);
            sts64(xsh + rr * SROW + 8 * l, c0r, c1r);
            cvt_f16(p1[rr], c0r, c1r);
            sts64(xsh + rr * SROW + 256 + 8 * l, c0r, c1r);
            float ss = sum8(p0[rr], p1[rr]);
            #pragma unroll
            for (int o = 16; o; o >>= 1) ss += __shfl_xor_sync(0xffffffffu, ss, o);
            if (l == 0) xinv_s[rbase + rr] = rsqrtf(ss);
        }
        // convert wave1
        #pragma unroll
        for (int rr = 0; rr < 4; rr++) {
            uint32_t c0r, c1r;
            cvt_f16(s0[rr], c0r, c1r);
            sts64(xsh + (4 + rr) * SROW + 8 * l, c0r, c1r);
            cvt_f16(s1[rr], c0r, c1r);
            sts64(xsh + (4 + rr) * SROW + 256 + 8 * l, c0r, c1r);
            float ss = sum8(s0[rr], s1[rr]);
            #pragma unroll
            for (int o = 16; o; o >>= 1) ss += __shfl_xor_sync(0xffffffffu, ss, o);
            if (l == 0) xinv_s[rbase + 4 + rr] = rsqrtf(ss);
        }
        // pair barrier: slice-q X writes (both warps) visible; partner's
        // ldsm reads of tile t-1 are done (WAR safe). Other pairs run free.
        asm volatile("bar.sync %0, %1;" :: "r"(barid), "r"(64) : "memory");

        // prefetch wave0 of next tile (latency covered by MMA below)
        int nt = tile + gridDim.x;
        if (nt < ntiles) {
            long long nb = (long long)nt * 64;
            #pragma unroll
            for (int rr = 0; rr < 4; rr++) {
                long long gr = nb + rbase + rr; if (gr >= B) gr = B - 1;
                const float4* px = (const float4*)(X + gr * 256);
                p0[rr] = __ldcs(px + l);
                p1[rr] = __ldcs(px + 32 + l);
            }
        }

        // MMA: 16 k-steps; warp computes 16 rows x 32 classes
        float acc[4][4];
        #pragma unroll
        for (int n = 0; n < 4; n++)
            #pragma unroll
            for (int j = 0; j < 4; j++) acc[n][j] = 0.0f;

        #pragma unroll
        for (int s = 0; s < 16; s++) {
            uint32_t a0, a1, a2, a3, b0, b1, b2, b3, c0, c1, c2, c3;
            ldsm4(xf + s * 32, a0, a1, a2, a3);
            ldsm4(af0 + s * 32, b0, b1, b2, b3);
            ldsm4(af1 + s * 32, c0, c1, c2, c3);
            mma16816(acc[0], a0, a1, a2, a3, b0, b2);
            mma16816(acc[1], a0, a1, a2, a3, b1, b3);
            mma16816(acc[2], a0, a1, a2, a3, c0, c2);
            mma16816(acc[3], a0, a1, a2, a3, c1, c3);
        }

        // epilogue — scale + streaming store (16 rows x 32 classes per warp)
        {
            int rloc = q * 16 + qr;
            float xi0 = xinv_s[rloc];
            float xi1 = xinv_s[rloc + 8];
            long long r0g = tb + rloc;
            float* o0 = out + r0g * 64;
            float* o1 = o0 + 8 * 64;
            #pragma unroll
            for (int n = 0; n < 4; n++) {
                int c0 = h * 32 + n * 8 + qc;
                float2 cn2 = *(const float2*)(cni_s + c0);
                int2   ff  = *(const int2*)(inf_s + c0);
                float2 v0, v1;
                v0.x = ff.x ? 1.0f : acc[n][0] * xi0 * cn2.x;
                v0.y = ff.y ? 1.0f : acc[n][1] * xi0 * cn2.y;
                v1.x = ff.x ? 1.0f : acc[n][2] * xi1 * cn2.x;
                v1.y = ff.y ? 1.0f : acc[n][3] * xi1 * cn2.y;
                if (r0g < B)     stg_cs64(o0 + c0, v0);
                if (r0g + 8 < B) stg_cs64(o1 + c0, v1);
            }
        }
        // pair barrier: both warps' ldsm reads + xinv reads of tile t done
        // before next iteration's STS to slice q (WAR).
        asm volatile("bar.sync %0, %1;" :: "r"(barid), "r"(64) : "memory");
    }
}

extern "C" void kernel_launch(void* const* d_in, const int* in_sizes, int n_in,
                              void* d_out, int out_size) {
    const float* X = (const float*)d_in[0];   // inputs [B, 256] fp32
    // d_in[1] = labels (unused)
    const float* A = (const float*)d_in[2];   // class_avgs [64, 256] fp32
    float* out = (float*)d_out;

    int B = in_sizes[0] / 256;
    int ntiles = (B + 63) / 64;

    int dev = 0, nsm = 148;
    cudaGetDevice(&dev);
    cudaDeviceGetAttribute(&nsm, cudaDevAttrMultiProcessorCount, dev);

    int grid = 3 * nsm;             // 3 CTAs/SM, 24 warps/SM
    if (grid > ntiles) grid = ntiles;

    cudaFuncSetAttribute(SimRel_48335561949951_kernel,
                         cudaFuncAttributeMaxDynamicSharedMemorySize, S_TOTAL);

    SimRel_48335561949951_kernel<<<grid, THREADS, S_TOTAL>>>(X, A, out, B, ntiles);
}

// round 13
// speedup vs baseline: 1.2799x; 1.0204x over previous
#include <cuda_runtime.h>
#include <cstdint>
#include <math.h>

// SimRel via single-pass fp16 mma.sync. R13: warp-AUTONOMOUS pipelines.
// Each warp owns a private 16-row X slice x all 64 classes (5 ldsm : 8 MMA,
// -17% ldsm wf vs R12) -> zero CTA barriers in the loop (only __syncwarp);
// 16 independent warp pipelines per SM hide each other's latency.
// 256 thr x 2 CTAs/SM (smem ~102KB, regs <=128). Row norms kept in registers.
// out = dot * rsqrt(|x|^2) * rsqrt(|a|^2) (norms exact fp32); 1.0 on inf rows.
// B=262144, D=256, C=64.

#define THREADS 256
#define SROW    528                 // 264 fp16 per row (256 + 8 pad), bytes

// ---- smem layout (bytes) ----
#define S_A     0                   // [64 x 264] fp16 centroids        33792
#define S_X     33792               // 8 slices x 16 rows x 528B        67584
#define S_CNI   101376              // [64] f32 centroid rsqrt norms      256
#define S_INF   101632              // [64] int inf flags                 256
#define S_TOTAL 101888              // x2 CTAs = 204KB <= 228KB/SM

__device__ __forceinline__ void sts64(uint32_t a, uint32_t x, uint32_t y) {
    asm volatile("st.shared.v2.b32 [%0], {%1,%2};" :: "r"(a), "r"(x), "r"(y));
}
__device__ __forceinline__ void ldsm4(uint32_t a, uint32_t& r0, uint32_t& r1,
                                      uint32_t& r2, uint32_t& r3) {
    asm volatile("ldmatrix.sync.aligned.m8n8.x4.shared.b16 {%0,%1,%2,%3}, [%4];"
                 : "=r"(r0), "=r"(r1), "=r"(r2), "=r"(r3) : "r"(a));
}
__device__ __forceinline__ void mma16816(float* c, uint32_t a0, uint32_t a1,
                                         uint32_t a2, uint32_t a3,
                                         uint32_t b0, uint32_t b1) {
    asm volatile("mma.sync.aligned.m16n8k16.row.col.f32.f16.f16.f32 "
                 "{%0,%1,%2,%3}, {%4,%5,%6,%7}, {%8,%9}, {%0,%1,%2,%3};"
                 : "+f"(c[0]), "+f"(c[1]), "+f"(c[2]), "+f"(c[3])
                 : "r"(a0), "r"(a1), "r"(a2), "r"(a3), "r"(b0), "r"(b1));
}
__device__ __forceinline__ void cvt_f16(float4 v, uint32_t& r0, uint32_t& r1) {
    asm("cvt.rn.f16x2.f32 %0, %1, %2;" : "=r"(r0) : "f"(v.y), "f"(v.x));
    asm("cvt.rn.f16x2.f32 %0, %1, %2;" : "=r"(r1) : "f"(v.w), "f"(v.z));
}
__device__ __forceinline__ void stg_cs64(float* p, float2 v) {
    asm volatile("st.global.cs.v2.f32 [%0], {%1,%2};" :: "l"(p), "f"(v.x), "f"(v.y));
}
__device__ __forceinline__ float sum8(float4 a, float4 b) {
    float s = a.x * a.x;
    s = fmaf(a.y, a.y, s); s = fmaf(a.z, a.z, s); s = fmaf(a.w, a.w, s);
    s = fmaf(b.x, b.x, s); s = fmaf(b.y, b.y, s);
    s = fmaf(b.z, b.z, s); s = fmaf(b.w, b.w, s);
    return s;
}

__global__ void __launch_bounds__(THREADS, 2)
SimRel_48335561949951_kernel(const float* __restrict__ X,
                             const float* __restrict__ A,
                             float* __restrict__ out,
                             int B, int ngroups) {
    extern __shared__ char smem[];
    const uint32_t sb = (uint32_t)__cvta_generic_to_shared(smem);
    float* cni_s = (float*)(smem + S_CNI);
    int*   inf_s = (int*)(smem + S_INF);

    const int tid = threadIdx.x, w = tid >> 5, l = tid & 31;

    // ---- centroid conversion + norms + inf flags (8 rows per warp, once) ----
    #pragma unroll
    for (int rr = 0; rr < 8; rr++) {
        int r = w * 8 + rr;
        const float4* pa = (const float4*)(A + (size_t)r * 256);
        float4 v0 = pa[l], v1 = pa[32 + l];
        uint32_t c0r, c1r;
        cvt_f16(v0, c0r, c1r);
        sts64(sb + S_A + r * SROW + 8 * l, c0r, c1r);
        cvt_f16(v1, c0r, c1r);
        sts64(sb + S_A + r * SROW + 256 + 8 * l, c0r, c1r);
        float ss = sum8(v0, v1);
        int bad = (fabsf(v0.x) == INFINITY) | (fabsf(v0.y) == INFINITY) |
                  (fabsf(v0.z) == INFINITY) | (fabsf(v0.w) == INFINITY) |
                  (fabsf(v1.x) == INFINITY) | (fabsf(v1.y) == INFINITY) |
                  (fabsf(v1.z) == INFINITY) | (fabsf(v1.w) == INFINITY);
        #pragma unroll
        for (int o = 16; o; o >>= 1) ss += __shfl_xor_sync(0xffffffffu, ss, o);
        unsigned m = __ballot_sync(0xffffffffu, bad);
        if (l == 0) { cni_s[r] = rsqrtf(ss); inf_s[r] = (m != 0); }
    }
    __syncthreads();   // A tile + cni/inf read-only hereafter

    // ---- per-lane ldmatrix fragment offsets ----
    const int t8 = l >> 3;
    const uint32_t frag_off = (uint32_t)(((t8 & 1) * 8 + (l & 7)) * SROW + (t8 >> 1) * 16);
    const uint32_t xslice = sb + S_X + (uint32_t)(w * 16) * SROW;  // private slice
    const uint32_t xf = xslice + frag_off;
    const uint32_t af = sb + S_A + frag_off;

    const int qr = l >> 2, qc = (l & 3) * 2;

    // global warp-group iteration (16 rows per group, warp-private)
    const long long gw = (long long)blockIdx.x * 8 + w;
    const long long gstride = (long long)gridDim.x * 8;

    float4 va[4], vb[4], wa[4], wb[4];

    // prologue: LDG wave0 (slice rows 0-3) of first group
    {
        long long gb = gw * 16;
        #pragma unroll
        for (int i = 0; i < 4; i++) {
            long long gr = gb + i; if (gr >= B) gr = B - 1;
            const float4* px = (const float4*)(X + gr * 256);
            va[i] = __ldcs(px + l);
            vb[i] = __ldcs(px + 32 + l);
        }
    }

    for (long long grp = gw; grp < ngroups; grp += gstride) {
        const long long gb = grp * 16;
        float xs0 = 1.0f, xs1 = 1.0f;   // squared norms for rows qr, qr+8

        // ---- convert 4 waves of 4 rows; LDG next wave early each time ----
        #pragma unroll
        for (int wv = 0; wv < 4; wv++) {
            // issue LDG of wave wv+1 (into the other buffer) before converting
            if (wv < 3) {
                #pragma unroll
                for (int i = 0; i < 4; i++) {
                    long long gr = gb + (wv + 1) * 4 + i; if (gr >= B) gr = B - 1;
                    const float4* px = (const float4*)(X + gr * 256);
                    if (wv & 1) { va[i] = __ldcs(px + l); vb[i] = __ldcs(px + 32 + l); }
                    else        { wa[i] = __ldcs(px + l); wb[i] = __ldcs(px + 32 + l); }
                }
            }
            const float4* ca = (wv & 1) ? wa : va;
            const float4* cb = (wv & 1) ? wb : vb;
            #pragma unroll
            for (int i = 0; i < 4; i++) {
                int srow = wv * 4 + i;
                uint32_t c0r, c1r;
                cvt_f16(ca[i], c0r, c1r);
                sts64(xslice + srow * SROW + 8 * l, c0r, c1r);
                cvt_f16(cb[i], c0r, c1r);
                sts64(xslice + srow * SROW + 256 + 8 * l, c0r, c1r);
                float ss = sum8(ca[i], cb[i]);
                #pragma unroll
                for (int o = 16; o; o >>= 1) ss += __shfl_xor_sync(0xffffffffu, ss, o);
                if (qr == srow)     xs0 = ss;
                if (qr + 8 == srow) xs1 = ss;
            }
        }
        __syncwarp();   // slice writes visible to all lanes for ldmatrix

        // ---- prefetch next group's wave0 (covered by MMA below) ----
        long long ng = grp + gstride;
        if (ng < ngroups) {
            long long nb = ng * 16;
            #pragma unroll
            for (int i = 0; i < 4; i++) {
                long long gr = nb + i; if (gr >= B) gr = B - 1;
                const float4* px = (const float4*)(X + gr * 256);
                va[i] = __ldcs(px + l);
                vb[i] = __ldcs(px + 32 + l);
            }
        }

        // ---- MMA: 16 k-steps; 16 rows x 64 classes per warp ----
        float acc[8][4];
        #pragma unroll
        for (int n = 0; n < 8; n++)
            #pragma unroll
            for (int j = 0; j < 4; j++) acc[n][j] = 0.0f;

        #pragma unroll
        for (int s = 0; s < 16; s++) {
            uint32_t a0, a1, a2, a3;
            ldsm4(xf + s * 32, a0, a1, a2, a3);
            #pragma unroll
            for (int hb = 0; hb < 4; hb++) {
                uint32_t b0, b1, b2, b3;
                ldsm4(af + hb * (16 * SROW) + s * 32, b0, b1, b2, b3);
                mma16816(acc[hb * 2 + 0], a0, a1, a2, a3, b0, b2);
                mma16816(acc[hb * 2 + 1], a0, a1, a2, a3, b1, b3);
            }
        }

        // ---- epilogue: scale + streaming store (16 rows x 64 classes) ----
        {
            float xi0 = rsqrtf(xs0);
            float xi1 = rsqrtf(xs1);
            long long r0g = gb + qr;
            float* o0 = out + r0g * 64;
            float* o1 = o0 + 8 * 64;
            #pragma unroll
            for (int n = 0; n < 8; n++) {
                int c0 = (n >> 1) * 16 + (n & 1) * 8 + qc;
                float2 cn2 = *(const float2*)(cni_s + c0);
                int2   ff  = *(const int2*)(inf_s + c0);
                float2 v0, v1;
                v0.x = ff.x ? 1.0f : acc[n][0] * xi0 * cn2.x;
                v0.y = ff.y ? 1.0f : acc[n][1] * xi0 * cn2.y;
                v1.x = ff.x ? 1.0f : acc[n][2] * xi1 * cn2.x;
                v1.y = ff.y ? 1.0f : acc[n][3] * xi1 * cn2.y;
                if (r0g < B)     stg_cs64(o0 + c0, v0);
                if (r0g + 8 < B) stg_cs64(o1 + c0, v1);
            }
        }
        // no barrier: slice is warp-private; program order + __syncwarp
        // at the top of the next iteration protects WAR on the slice.
    }
}

extern "C" void kernel_launch(void* const* d_in, const int* in_sizes, int n_in,
                              void* d_out, int out_size) {
    const float* X = (const float*)d_in[0];   // inputs [B, 256] fp32
    // d_in[1] = labels (unused)
    const float* A = (const float*)d_in[2];   // class_avgs [64, 256] fp32
    float* out = (float*)d_out;

    int B = in_sizes[0] / 256;
    int ngroups = (B + 15) / 16;

    int dev = 0, nsm = 148;
    cudaGetDevice(&dev);
    cudaDeviceGetAttribute(&nsm, cudaDevAttrMultiProcessorCount, dev);

    int grid = 2 * nsm;             // 2 CTAs/SM, 16 autonomous warps/SM
    long long totalw = (long long)grid * 8;
    if (totalw > ngroups) grid = (int)((ngroups + 7) / 8);

    cudaFuncSetAttribute(SimRel_48335561949951_kernel,
                         cudaFuncAttributeMaxDynamicSharedMemorySize, S_TOTAL);

    SimRel_48335561949951_kernel<<<grid, THREADS, S_TOTAL>>>(X, A, out, B, ngroups);
}

// round 15
// speedup vs baseline: 1.3099x; 1.0234x over previous
#include <cuda_runtime.h>
#include <cstdint>
#include <math.h>

// SimRel via single-pass fp16 mma.sync. R15 = R14 with the buffer-role swap
// fixed: next-group wave0 now lands in va (consumed as slice rows 0-3) and
// wave1 in wa (rows 4-7), matching the loop head. R14 had them crossed ->
// rows 0-3/4-7 exchanged from group 2 onward (rel_err 0.92).
//  (1) batched norm reduction: 28 SHFL/group instead of 80 (-25% MIO)
//  (2) two-wave cross-group register prefetch: every LDG wave covered
//      >=300cyc (waves 0/1 of next group by the whole MMA phase)
//  (3) int32 indexing + IMNMX clamps.
// 256 thr x 2 CTAs/SM, warp-autonomous 16x64 pipelines, no CTA barriers.
// out = dot * rsqrt(|x|^2) * rsqrt(|a|^2); 1.0 on inf. B=262144, D=256, C=64.

#define THREADS 256
#define SROW    528                 // 264 fp16 per row (256 + 8 pad), bytes
#define FULLM   0xffffffffu

// ---- smem layout (bytes) ----
#define S_A     0                   // [64 x 264] fp16 centroids        33792
#define S_X     33792               // 8 slices x 16 rows x 528B        67584
#define S_CNI   101376              // [64] f32 centroid rsqrt norms      256
#define S_INF   101632              // [64] int inf flags                 256
#define S_TOTAL 101888              // x2 CTAs = 204KB <= 228KB/SM

__device__ __forceinline__ void sts64(uint32_t a, uint32_t x, uint32_t y) {
    asm volatile("st.shared.v2.b32 [%0], {%1,%2};" :: "r"(a), "r"(x), "r"(y));
}
__device__ __forceinline__ void ldsm4(uint32_t a, uint32_t& r0, uint32_t& r1,
                                      uint32_t& r2, uint32_t& r3) {
    asm volatile("ldmatrix.sync.aligned.m8n8.x4.shared.b16 {%0,%1,%2,%3}, [%4];"
                 : "=r"(r0), "=r"(r1), "=r"(r2), "=r"(r3) : "r"(a));
}
__device__ __forceinline__ void mma16816(float* c, uint32_t a0, uint32_t a1,
                                         uint32_t a2, uint32_t a3,
                                         uint32_t b0, uint32_t b1) {
    asm volatile("mma.sync.aligned.m16n8k16.row.col.f32.f16.f16.f32 "
                 "{%0,%1,%2,%3}, {%4,%5,%6,%7}, {%8,%9}, {%0,%1,%2,%3};"
                 : "+f"(c[0]), "+f"(c[1]), "+f"(c[2]), "+f"(c[3])
                 : "r"(a0), "r"(a1), "r"(a2), "r"(a3), "r"(b0), "r"(b1));
}
__device__ __forceinline__ void cvt_f16(float4 v, uint32_t& r0, uint32_t& r1) {
    asm("cvt.rn.f16x2.f32 %0, %1, %2;" : "=r"(r0) : "f"(v.y), "f"(v.x));
    asm("cvt.rn.f16x2.f32 %0, %1, %2;" : "=r"(r1) : "f"(v.w), "f"(v.z));
}
__device__ __forceinline__ void stg_cs64(float* p, float2 v) {
    asm volatile("st.global.cs.v2.f32 [%0], {%1,%2};" :: "l"(p), "f"(v.x), "f"(v.y));
}
__device__ __forceinline__ float sum8(float4 a, float4 b) {
    float s = a.x * a.x;
    s = fmaf(a.y, a.y, s); s = fmaf(a.z, a.z, s); s = fmaf(a.w, a.w, s);
    s = fmaf(b.x, b.x, s); s = fmaf(b.y, b.y, s);
    s = fmaf(b.z, b.z, s); s = fmaf(b.w, b.w, s);
    return s;
}

// Load one 4-row wave (rows rowbase..rowbase+3), lane l takes float4 l and 32+l.
#define LOADW(A0, B0, rowbase) do {                                      \
    _Pragma("unroll")                                                    \
    for (int _i = 0; _i < 4; _i++) {                                     \
        int _gr = min((rowbase) + _i, Bm1);                              \
        const float4* _px = (const float4*)(X + (size_t)_gr * 256);      \
        (A0)[_i] = __ldcs(_px + l);                                      \
        (B0)[_i] = __ldcs(_px + 32 + l);                                 \
    }                                                                    \
} while (0)

// Convert one wave (4 rows) into the slice at rows wvbase.., and batch-reduce
// the 4 row-norms into rwv: full sum of row (wvbase + (l&3)) in every lane.
#define CONVW(A0, B0, wvbase, rwv) do {                                  \
    float _ss[4];                                                        \
    _Pragma("unroll")                                                    \
    for (int _i = 0; _i < 4; _i++) {                                     \
        uint32_t _c0, _c1;                                               \
        cvt_f16((A0)[_i], _c0, _c1);                                     \
        sts64(xslice + ((wvbase) + _i) * SROW + 8 * l, _c0, _c1);        \
        cvt_f16((B0)[_i], _c0, _c1);                                     \
        sts64(xslice + ((wvbase) + _i) * SROW + 256 + 8 * l, _c0, _c1);  \
        _ss[_i] = sum8((A0)[_i], (B0)[_i]);                              \
    }                                                                    \
    float _t, _a01, _a23, _b;                                            \
    _t = __shfl_xor_sync(FULLM, (l & 1) ? _ss[0] : _ss[1], 1);           \
    _a01 = ((l & 1) ? _ss[1] : _ss[0]) + _t;                             \
    _t = __shfl_xor_sync(FULLM, (l & 1) ? _ss[2] : _ss[3], 1);           \
    _a23 = ((l & 1) ? _ss[3] : _ss[2]) + _t;                             \
    _t = __shfl_xor_sync(FULLM, (l & 2) ? _a01 : _a23, 2);               \
    _b = ((l & 2) ? _a23 : _a01) + _t;                                   \
    _b += __shfl_xor_sync(FULLM, _b, 4);                                 \
    _b += __shfl_xor_sync(FULLM, _b, 8);                                 \
    _b += __shfl_xor_sync(FULLM, _b, 16);                                \
    (rwv) = _b;                                                          \
} while (0)

__global__ void __launch_bounds__(THREADS, 2)
SimRel_48335561949951_kernel(const float* __restrict__ X,
                             const float* __restrict__ A,
                             float* __restrict__ out,
                             int B, int ngroups) {
    extern __shared__ char smem[];
    const uint32_t sb = (uint32_t)__cvta_generic_to_shared(smem);
    float* cni_s = (float*)(smem + S_CNI);
    int*   inf_s = (int*)(smem + S_INF);

    const int tid = threadIdx.x, w = tid >> 5, l = tid & 31;
    const int Bm1 = B - 1;

    // ---- centroid conversion + norms + inf flags (8 rows per warp, once) ----
    #pragma unroll
    for (int rr = 0; rr < 8; rr++) {
        int r = w * 8 + rr;
        const float4* pa = (const float4*)(A + (size_t)r * 256);
        float4 v0 = pa[l], v1 = pa[32 + l];
        uint32_t c0r, c1r;
        cvt_f16(v0, c0r, c1r);
        sts64(sb + S_A + r * SROW + 8 * l, c0r, c1r);
        cvt_f16(v1, c0r, c1r);
        sts64(sb + S_A + r * SROW + 256 + 8 * l, c0r, c1r);
        float ss = sum8(v0, v1);
        int bad = (fabsf(v0.x) == INFINITY) | (fabsf(v0.y) == INFINITY) |
                  (fabsf(v0.z) == INFINITY) | (fabsf(v0.w) == INFINITY) |
                  (fabsf(v1.x) == INFINITY) | (fabsf(v1.y) == INFINITY) |
                  (fabsf(v1.z) == INFINITY) | (fabsf(v1.w) == INFINITY);
        #pragma unroll
        for (int o = 16; o; o >>= 1) ss += __shfl_xor_sync(FULLM, ss, o);
        unsigned m = __ballot_sync(FULLM, bad);
        if (l == 0) { cni_s[r] = rsqrtf(ss); inf_s[r] = (m != 0); }
    }
    __syncthreads();   // A tile + cni/inf read-only hereafter

    // ---- per-lane ldmatrix fragment offsets ----
    const int t8 = l >> 3;
    const uint32_t frag_off = (uint32_t)(((t8 & 1) * 8 + (l & 7)) * SROW + (t8 >> 1) * 16);
    const uint32_t xslice = sb + S_X + (uint32_t)(w * 16) * SROW;  // private slice
    const uint32_t xf = xslice + frag_off;
    const uint32_t af = sb + S_A + frag_off;

    const int qr = l >> 2, qc = (l & 3) * 2;

    const int gw = blockIdx.x * 8 + w;
    const int gstride = gridDim.x * 8;

    float4 va[4], vb[4], wa[4], wb[4];

    // prologue: LDG waves 0,1 of first group (va = wave0, wa = wave1)
    LOADW(va, vb, gw * 16);
    LOADW(wa, wb, gw * 16 + 4);

    for (int grp = gw; grp < ngroups; grp += gstride) {
        const int gb = grp * 16;
        const int ng = grp + gstride;
        const int has_next = (ng < ngroups);
        const int nb = ng * 16;

        float rw0, rw1, rw2, rw3;
        {
            float4 ta[4], tb[4];                 // third buffer (aliases dead acc)
            LOADW(ta, tb, gb + 8);               // wave2: covered by conv w0+w1
            CONVW(va, vb, 0, rw0);               // convert wave0 (frees va)
            LOADW(va, vb, gb + 12);              // wave3 into va: cover by w1+w2
            CONVW(wa, wb, 4, rw1);               // convert wave1 (frees wa)
            if (has_next) LOADW(wa, wb, nb + 4); // next WAVE1 -> wa (MMA covers)
            CONVW(ta, tb, 8, rw2);               // convert wave2
            CONVW(va, vb, 12, rw3);              // convert wave3 (frees va)
            if (has_next) LOADW(va, vb, nb);     // next WAVE0 -> va (MMA covers)
        }
        // redistribute row norms: xs0 = |row qr|^2, xs1 = |row qr+8|^2
        float s0a = __shfl_sync(FULLM, rw0, qr);
        float s0b = __shfl_sync(FULLM, rw1, qr);
        float s1a = __shfl_sync(FULLM, rw2, qr);
        float s1b = __shfl_sync(FULLM, rw3, qr);
        float xs0 = (qr < 4) ? s0a : s0b;
        float xs1 = (qr < 4) ? s1a : s1b;

        __syncwarp();   // slice writes visible to all lanes for ldmatrix

        // ---- MMA: 16 k-steps; 16 rows x 64 classes per warp ----
        float acc[8][4];
        #pragma unroll
        for (int n = 0; n < 8; n++)
            #pragma unroll
            for (int j = 0; j < 4; j++) acc[n][j] = 0.0f;

        #pragma unroll
        for (int s = 0; s < 16; s++) {
            uint32_t a0, a1, a2, a3;
            ldsm4(xf + s * 32, a0, a1, a2, a3);
            #pragma unroll
            for (int hb = 0; hb < 4; hb++) {
                uint32_t b0, b1, b2, b3;
                ldsm4(af + hb * (16 * SROW) + s * 32, b0, b1, b2, b3);
                mma16816(acc[hb * 2 + 0], a0, a1, a2, a3, b0, b2);
                mma16816(acc[hb * 2 + 1], a0, a1, a2, a3, b1, b3);
            }
        }

        // ---- epilogue: scale + streaming store (16 rows x 64 classes) ----
        {
            float xi0 = rsqrtf(xs0);
            float xi1 = rsqrtf(xs1);
            int r0g = gb + qr;
            float* o0 = out + (size_t)r0g * 64;
            float* o1 = o0 + 8 * 64;
            bool g0 = (r0g < B), g1 = (r0g + 8 < B);
            #pragma unroll
            for (int n = 0; n < 8; n++) {
                int c0 = (n >> 1) * 16 + (n & 1) * 8 + qc;
                float2 cn2 = *(const float2*)(cni_s + c0);
                int2   ff  = *(const int2*)(inf_s + c0);
                float2 v0, v1;
                v0.x = ff.x ? 1.0f : acc[n][0] * xi0 * cn2.x;
                v0.y = ff.y ? 1.0f : acc[n][1] * xi0 * cn2.y;
                v1.x = ff.x ? 1.0f : acc[n][2] * xi1 * cn2.x;
                v1.y = ff.y ? 1.0f : acc[n][3] * xi1 * cn2.y;
                if (g0) stg_cs64(o0 + c0, v0);
                if (g1) stg_cs64(o1 + c0, v1);
            }
        }
        // no barrier: slice is warp-private; __syncwarp above orders the
        // next iteration's STS after this iteration's ldsm reads (WAR).
    }
}

extern "C" void kernel_launch(void* const* d_in, const int* in_sizes, int n_in,
                              void* d_out, int out_size) {
    const float* X = (const float*)d_in[0];   // inputs [B, 256] fp32
    // d_in[1] = labels (unused)
    const float* A = (const float*)d_in[2];   // class_avgs [64, 256] fp32
    float* out = (float*)d_out;

    int B = in_sizes[0] / 256;
    int ngroups = (B + 15) / 16;

    int dev = 0, nsm = 148;
    cudaGetDevice(&dev);
    cudaDeviceGetAttribute(&nsm, cudaDevAttrMultiProcessorCount, dev);

    int grid = 2 * nsm;             // 2 CTAs/SM, 16 autonomous warps/SM
    if ((long long)grid * 8 > ngroups) grid = (ngroups + 7) / 8;

    cudaFuncSetAttribute(SimRel_48335561949951_kernel,
                         cudaFuncAttributeMaxDynamicSharedMemorySize, S_TOTAL);

    SimRel_48335561949951_kernel<<<grid, THREADS, S_TOTAL>>>(X, A, out, B, ngroups);
}

// round 16
// speedup vs baseline: 1.3171x; 1.0055x over previous
#include <cuda_runtime.h>
#include <cstdint>
#include <math.h>

// SimRel via single-pass fp16 mma.sync. R16 = R15 + deferred norm reduction:
// convert does only the 3 pack-exchange shuffle stages per wave (partial per
// wave in a register); the 3 deep butterfly rounds (4 independent chains),
// redistribution shfls and rsqrtf are executed BETWEEN MMA k-steps 3 and 4,
// hiding ~500+ cyc of shuffle latency under ldsm/tensor work.
// 256 thr x 2 CTAs/SM, warp-autonomous 16x64 pipelines, no CTA barriers.
// out = dot * rsqrt(|x|^2) * rsqrt(|a|^2); 1.0 on inf. B=262144, D=256, C=64.

#define THREADS 256
#define SROW    528                 // 264 fp16 per row (256 + 8 pad), bytes
#define FULLM   0xffffffffu

// ---- smem layout (bytes) ----
#define S_A     0                   // [64 x 264] fp16 centroids        33792
#define S_X     33792               // 8 slices x 16 rows x 528B        67584
#define S_CNI   101376              // [64] f32 centroid rsqrt norms      256
#define S_INF   101632              // [64] int inf flags                 256
#define S_TOTAL 101888              // x2 CTAs = 204KB <= 228KB/SM

__device__ __forceinline__ void sts64(uint32_t a, uint32_t x, uint32_t y) {
    asm volatile("st.shared.v2.b32 [%0], {%1,%2};" :: "r"(a), "r"(x), "r"(y));
}
__device__ __forceinline__ void ldsm4(uint32_t a, uint32_t& r0, uint32_t& r1,
                                      uint32_t& r2, uint32_t& r3) {
    asm volatile("ldmatrix.sync.aligned.m8n8.x4.shared.b16 {%0,%1,%2,%3}, [%4];"
                 : "=r"(r0), "=r"(r1), "=r"(r2), "=r"(r3) : "r"(a));
}
__device__ __forceinline__ void mma16816(float* c, uint32_t a0, uint32_t a1,
                                         uint32_t a2, uint32_t a3,
                                         uint32_t b0, uint32_t b1) {
    asm volatile("mma.sync.aligned.m16n8k16.row.col.f32.f16.f16.f32 "
                 "{%0,%1,%2,%3}, {%4,%5,%6,%7}, {%8,%9}, {%0,%1,%2,%3};"
                 : "+f"(c[0]), "+f"(c[1]), "+f"(c[2]), "+f"(c[3])
                 : "r"(a0), "r"(a1), "r"(a2), "r"(a3), "r"(b0), "r"(b1));
}
__device__ __forceinline__ void cvt_f16(float4 v, uint32_t& r0, uint32_t& r1) {
    asm("cvt.rn.f16x2.f32 %0, %1, %2;" : "=r"(r0) : "f"(v.y), "f"(v.x));
    asm("cvt.rn.f16x2.f32 %0, %1, %2;" : "=r"(r1) : "f"(v.w), "f"(v.z));
}
__device__ __forceinline__ void stg_cs64(float* p, float2 v) {
    asm volatile("st.global.cs.v2.f32 [%0], {%1,%2};" :: "l"(p), "f"(v.x), "f"(v.y));
}
__device__ __forceinline__ float sum8(float4 a, float4 b) {
    float s = a.x * a.x;
    s = fmaf(a.y, a.y, s); s = fmaf(a.z, a.z, s); s = fmaf(a.w, a.w, s);
    s = fmaf(b.x, b.x, s); s = fmaf(b.y, b.y, s);
    s = fmaf(b.z, b.z, s); s = fmaf(b.w, b.w, s);
    return s;
}

// Load one 4-row wave (rows rowbase..rowbase+3), lane l takes float4 l and 32+l.
#define LOADW(A0, B0, rowbase) do {                                      \
    _Pragma("unroll")                                                    \
    for (int _i = 0; _i < 4; _i++) {                                     \
        int _gr = min((rowbase) + _i, Bm1);                              \
        const float4* _px = (const float4*)(X + (size_t)_gr * 256);      \
        (A0)[_i] = __ldcs(_px + l);                                      \
        (B0)[_i] = __ldcs(_px + 32 + l);                                 \
    }                                                                    \
} while (0)

// Convert one wave (4 rows) into the slice at rows wvbase.. and produce the
// QUAD-PARTIAL norm rwv: lane l holds the partial sum of row (wvbase+(l&3))
// over its 4-lane quad. Deep butterflies (xor 4/8/16) are deferred.
#define CONVW2(A0, B0, wvbase, rwv) do {                                 \
    float _ss[4];                                                        \
    _Pragma("unroll")                                                    \
    for (int _i = 0; _i < 4; _i++) {                                     \
        uint32_t _c0, _c1;                                               \
        cvt_f16((A0)[_i], _c0, _c1);                                     \
        sts64(xslice + ((wvbase) + _i) * SROW + 8 * l, _c0, _c1);        \
        cvt_f16((B0)[_i], _c0, _c1);                                     \
        sts64(xslice + ((wvbase) + _i) * SROW + 256 + 8 * l, _c0, _c1);  \
        _ss[_i] = sum8((A0)[_i], (B0)[_i]);                              \
    }                                                                    \
    float _t, _a01, _a23;                                                \
    _t = __shfl_xor_sync(FULLM, (l & 1) ? _ss[0] : _ss[1], 1);           \
    _a01 = ((l & 1) ? _ss[1] : _ss[0]) + _t;                             \
    _t = __shfl_xor_sync(FULLM, (l & 1) ? _ss[2] : _ss[3], 1);           \
    _a23 = ((l & 1) ? _ss[3] : _ss[2]) + _t;                             \
    _t = __shfl_xor_sync(FULLM, (l & 2) ? _a01 : _a23, 2);               \
    (rwv) = ((l & 2) ? _a23 : _a01) + _t;                                \
} while (0)

// One MMA k-step: 1 X ldsm4 + 4 A ldsm4 + 8 mma.
#define KSTEP(s) do {                                                    \
    uint32_t _a0, _a1, _a2, _a3;                                         \
    ldsm4(xf + (s) * 32, _a0, _a1, _a2, _a3);                            \
    _Pragma("unroll")                                                    \
    for (int _hb = 0; _hb < 4; _hb++) {                                  \
        uint32_t _b0, _b1, _b2, _b3;                                     \
        ldsm4(af + _hb * (16 * SROW) + (s) * 32, _b0, _b1, _b2, _b3);    \
        mma16816(acc[_hb * 2 + 0], _a0, _a1, _a2, _a3, _b0, _b2);        \
        mma16816(acc[_hb * 2 + 1], _a0, _a1, _a2, _a3, _b1, _b3);        \
    }                                                                    \
} while (0)

__global__ void __launch_bounds__(THREADS, 2)
SimRel_48335561949951_kernel(const float* __restrict__ X,
                             const float* __restrict__ A,
                             float* __restrict__ out,
                             int B, int ngroups) {
    extern __shared__ char smem[];
    const uint32_t sb = (uint32_t)__cvta_generic_to_shared(smem);
    float* cni_s = (float*)(smem + S_CNI);
    int*   inf_s = (int*)(smem + S_INF);

    const int tid = threadIdx.x, w = tid >> 5, l = tid & 31;
    const int Bm1 = B - 1;

    // ---- centroid conversion + norms + inf flags (8 rows per warp, once) ----
    #pragma unroll
    for (int rr = 0; rr < 8; rr++) {
        int r = w * 8 + rr;
        const float4* pa = (const float4*)(A + (size_t)r * 256);
        float4 v0 = pa[l], v1 = pa[32 + l];
        uint32_t c0r, c1r;
        cvt_f16(v0, c0r, c1r);
        sts64(sb + S_A + r * SROW + 8 * l, c0r, c1r);
        cvt_f16(v1, c0r, c1r);
        sts64(sb + S_A + r * SROW + 256 + 8 * l, c0r, c1r);
        float ss = sum8(v0, v1);
        int bad = (fabsf(v0.x) == INFINITY) | (fabsf(v0.y) == INFINITY) |
                  (fabsf(v0.z) == INFINITY) | (fabsf(v0.w) == INFINITY) |
                  (fabsf(v1.x) == INFINITY) | (fabsf(v1.y) == INFINITY) |
                  (fabsf(v1.z) == INFINITY) | (fabsf(v1.w) == INFINITY);
        #pragma unroll
        for (int o = 16; o; o >>= 1) ss += __shfl_xor_sync(FULLM, ss, o);
        unsigned m = __ballot_sync(FULLM, bad);
        if (l == 0) { cni_s[r] = rsqrtf(ss); inf_s[r] = (m != 0); }
    }
    __syncthreads();   // A tile + cni/inf read-only hereafter

    // ---- per-lane ldmatrix fragment offsets ----
    const int t8 = l >> 3;
    const uint32_t frag_off = (uint32_t)(((t8 & 1) * 8 + (l & 7)) * SROW + (t8 >> 1) * 16);
    const uint32_t xslice = sb + S_X + (uint32_t)(w * 16) * SROW;  // private slice
    const uint32_t xf = xslice + frag_off;
    const uint32_t af = sb + S_A + frag_off;

    const int qr = l >> 2, qc = (l & 3) * 2;

    const int gw = blockIdx.x * 8 + w;
    const int gstride = gridDim.x * 8;

    float4 va[4], vb[4], wa[4], wb[4];

    // prologue: LDG waves 0,1 of first group (va = wave0, wa = wave1)
    LOADW(va, vb, gw * 16);
    LOADW(wa, wb, gw * 16 + 4);

    for (int grp = gw; grp < ngroups; grp += gstride) {
        const int gb = grp * 16;
        const int ng = grp + gstride;
        const int has_next = (ng < ngroups);
        const int nb = ng * 16;

        float rw0, rw1, rw2, rw3;   // quad-partial row norms (deep stages deferred)
        {
            float4 ta[4], tb[4];                 // third buffer (aliases dead acc)
            LOADW(ta, tb, gb + 8);               // wave2: covered by conv w0+w1
            CONVW2(va, vb, 0, rw0);              // convert wave0 (frees va)
            LOADW(va, vb, gb + 12);              // wave3 into va: cover by w1+w2
            CONVW2(wa, wb, 4, rw1);              // convert wave1 (frees wa)
            if (has_next) LOADW(wa, wb, nb + 4); // next WAVE1 -> wa (MMA covers)
            CONVW2(ta, tb, 8, rw2);              // convert wave2
            CONVW2(va, vb, 12, rw3);             // convert wave3 (frees va)
            if (has_next) LOADW(va, vb, nb);     // next WAVE0 -> va (MMA covers)
        }

        __syncwarp();   // slice writes visible to all lanes for ldmatrix

        // ---- MMA: 16 k-steps; 16 rows x 64 classes per warp ----
        float acc[8][4];
        #pragma unroll
        for (int n = 0; n < 8; n++)
            #pragma unroll
            for (int j = 0; j < 4; j++) acc[n][j] = 0.0f;

        #pragma unroll
        for (int s = 0; s < 4; s++) KSTEP(s);

        // deferred norm finish: 3 butterfly rounds x 4 independent chains,
        // then redistribution + rsqrt — all hidden under the next 12 k-steps.
        #pragma unroll
        for (int o = 4; o <= 16; o <<= 1) {
            rw0 += __shfl_xor_sync(FULLM, rw0, o);
            rw1 += __shfl_xor_sync(FULLM, rw1, o);
            rw2 += __shfl_xor_sync(FULLM, rw2, o);
            rw3 += __shfl_xor_sync(FULLM, rw3, o);
        }
        float s0a = __shfl_sync(FULLM, rw0, qr);
        float s0b = __shfl_sync(FULLM, rw1, qr);
        float s1a = __shfl_sync(FULLM, rw2, qr);
        float s1b = __shfl_sync(FULLM, rw3, qr);
        float xi0 = rsqrtf((qr < 4) ? s0a : s0b);
        float xi1 = rsqrtf((qr < 4) ? s1a : s1b);

        #pragma unroll
        for (int s = 4; s < 16; s++) KSTEP(s);

        // ---- epilogue: scale + streaming store (16 rows x 64 classes) ----
        {
            int r0g = gb + qr;
            float* o0 = out + (size_t)r0g * 64;
            float* o1 = o0 + 8 * 64;
            bool g0 = (r0g < B), g1 = (r0g + 8 < B);
            #pragma unroll
            for (int n = 0; n < 8; n++) {
                int c0 = (n >> 1) * 16 + (n & 1) * 8 + qc;
                float2 cn2 = *(const float2*)(cni_s + c0);
                int2   ff  = *(const int2*)(inf_s + c0);
                float2 v0, v1;
                v0.x = ff.x ? 1.0f : acc[n][0] * xi0 * cn2.x;
                v0.y = ff.y ? 1.0f : acc[n][1] * xi0 * cn2.y;
                v1.x = ff.x ? 1.0f : acc[n][2] * xi1 * cn2.x;
                v1.y = ff.y ? 1.0f : acc[n][3] * xi1 * cn2.y;
                if (g0) stg_cs64(o0 + c0, v0);
                if (g1) stg_cs64(o1 + c0, v1);
            }
        }
        // no barrier: slice is warp-private; __syncwarp above orders the
        // next iteration's STS after this iteration's ldsm reads (WAR).
    }
}

extern "C" void kernel_launch(void* const* d_in, const int* in_sizes, int n_in,
                              void* d_out, int out_size) {
    const float* X = (const float*)d_in[0];   // inputs [B, 256] fp32
    // d_in[1] = labels (unused)
    const float* A = (const float*)d_in[2];   // class_avgs [64, 256] fp32
    float* out = (float*)d_out;

    int B = in_sizes[0] / 256;
    int ngroups = (B + 15) / 16;

    int dev = 0, nsm = 148;
    cudaGetDevice(&dev);
    cudaDeviceGetAttribute(&nsm, cudaDevAttrMultiProcessorCount, dev);

    int grid = 2 * nsm;             // 2 CTAs/SM, 16 autonomous warps/SM
    if ((long long)grid * 8 > ngroups) grid = (ngroups + 7) / 8;

    cudaFuncSetAttribute(SimRel_48335561949951_kernel,
                         cudaFuncAttributeMaxDynamicSharedMemorySize, S_TOTAL);

    SimRel_48335561949951_kernel<<<grid, THREADS, S_TOTAL>>>(X, A, out, B, ngroups);
}

// round 17
// speedup vs baseline: 1.3316x; 1.0111x over previous
#include <cuda_runtime.h>
#include <cstdint>
#include <math.h>

// SimRel via single-pass fp16 mma.sync. R17: pair-shared M=32 x N=32 warp
// tiles. Two warps share a 32-row X slice (each converts 16 rows); each warp
// owns a 32-class A half. Per k-step: 2 X-ldsm + 2 A-ldsm -> 8 MMAs.
// A-tile smem re-reads amortize over 32 rows: total ldsm bytes/16 rows drop
// 40KB -> 32KB (-20%). Pair barriers (R12-proven) replace __syncwarp; R15's
// 4-wave LDG pipeline with cross-group prefetch kept unchanged.
// 256 thr x 2 CTAs/SM. out = dot * rsqrt(|x|^2) * rsqrt(|a|^2); 1.0 on inf.
// B=262144, D=256, C=64.

#define THREADS 256
#define SROW    528                 // 264 fp16 per row (256 + 8 pad), bytes
#define FULLM   0xffffffffu

// ---- smem layout (bytes) ----
#define S_A     0                   // [64 x 264] fp16 centroids        33792
#define S_X     33792               // 4 pair-slices x 32 rows x 528B   67584
#define S_XINV  101376              // [128] f32 row rsqrt norms          512
#define S_CNI   101888              // [64] f32 centroid rsqrt norms      256
#define S_INF   102144              // [64] int inf flags                 256
#define S_TOTAL 102400              // x2 CTAs = 204.8KB <= 228KB/SM

__device__ __forceinline__ void sts64(uint32_t a, uint32_t x, uint32_t y) {
    asm volatile("st.shared.v2.b32 [%0], {%1,%2};" :: "r"(a), "r"(x), "r"(y));
}
__device__ __forceinline__ void ldsm4(uint32_t a, uint32_t& r0, uint32_t& r1,
                                      uint32_t& r2, uint32_t& r3) {
    asm volatile("ldmatrix.sync.aligned.m8n8.x4.shared.b16 {%0,%1,%2,%3}, [%4];"
                 : "=r"(r0), "=r"(r1), "=r"(r2), "=r"(r3) : "r"(a));
}
__device__ __forceinline__ void mma16816(float* c, uint32_t a0, uint32_t a1,
                                         uint32_t a2, uint32_t a3,
                                         uint32_t b0, uint32_t b1) {
    asm volatile("mma.sync.aligned.m16n8k16.row.col.f32.f16.f16.f32 "
                 "{%0,%1,%2,%3}, {%4,%5,%6,%7}, {%8,%9}, {%0,%1,%2,%3};"
                 : "+f"(c[0]), "+f"(c[1]), "+f"(c[2]), "+f"(c[3])
                 : "r"(a0), "r"(a1), "r"(a2), "r"(a3), "r"(b0), "r"(b1));
}
__device__ __forceinline__ void cvt_f16(float4 v, uint32_t& r0, uint32_t& r1) {
    asm("cvt.rn.f16x2.f32 %0, %1, %2;" : "=r"(r0) : "f"(v.y), "f"(v.x));
    asm("cvt.rn.f16x2.f32 %0, %1, %2;" : "=r"(r1) : "f"(v.w), "f"(v.z));
}
__device__ __forceinline__ void stg_cs64(float* p, float2 v) {
    asm volatile("st.global.cs.v2.f32 [%0], {%1,%2};" :: "l"(p), "f"(v.x), "f"(v.y));
}
__device__ __forceinline__ float sum8(float4 a, float4 b) {
    float s = a.x * a.x;
    s = fmaf(a.y, a.y, s); s = fmaf(a.z, a.z, s); s = fmaf(a.w, a.w, s);
    s = fmaf(b.x, b.x, s); s = fmaf(b.y, b.y, s);
    s = fmaf(b.z, b.z, s); s = fmaf(b.w, b.w, s);
    return s;
}

// Load one 4-row wave (rows rowbase..rowbase+3), lane l takes float4 l and 32+l.
#define LOADW(A0, B0, rowbase) do {                                      \
    _Pragma("unroll")                                                    \
    for (int _i = 0; _i < 4; _i++) {                                     \
        int _gr = min((rowbase) + _i, Bm1);                              \
        const float4* _px = (const float4*)(X + (size_t)_gr * 256);      \
        (A0)[_i] = __ldcs(_px + l);                                      \
        (B0)[_i] = __ldcs(_px + 32 + l);                                 \
    }                                                                    \
} while (0)

// Convert one wave (4 rows) into the warp's write region at rows wvbase..,
// and fully reduce the 4 row-norms: rwv = |row wvbase+(l&3)|^2 in every lane.
#define CONVW(A0, B0, wvbase, rwv) do {                                  \
    float _ss[4];                                                        \
    _Pragma("unroll")                                                    \
    for (int _i = 0; _i < 4; _i++) {                                     \
        uint32_t _c0, _c1;                                               \
        cvt_f16((A0)[_i], _c0, _c1);                                     \
        sts64(xwr + ((wvbase) + _i) * SROW + 8 * l, _c0, _c1);           \
        cvt_f16((B0)[_i], _c0, _c1);                                     \
        sts64(xwr + ((wvbase) + _i) * SROW + 256 + 8 * l, _c0, _c1);     \
        _ss[_i] = sum8((A0)[_i], (B0)[_i]);                              \
    }                                                                    \
    float _t, _a01, _a23, _b;                                            \
    _t = __shfl_xor_sync(FULLM, (l & 1) ? _ss[0] : _ss[1], 1);           \
    _a01 = ((l & 1) ? _ss[1] : _ss[0]) + _t;                             \
    _t = __shfl_xor_sync(FULLM, (l & 1) ? _ss[2] : _ss[3], 1);           \
    _a23 = ((l & 1) ? _ss[3] : _ss[2]) + _t;                             \
    _t = __shfl_xor_sync(FULLM, (l & 2) ? _a01 : _a23, 2);               \
    _b = ((l & 2) ? _a23 : _a01) + _t;                                   \
    _b += __shfl_xor_sync(FULLM, _b, 4);                                 \
    _b += __shfl_xor_sync(FULLM, _b, 8);                                 \
    _b += __shfl_xor_sync(FULLM, _b, 16);                                \
    (rwv) = _b;                                                          \
} while (0)

__global__ void __launch_bounds__(THREADS, 2)
SimRel_48335561949951_kernel(const float* __restrict__ X,
                             const float* __restrict__ A,
                             float* __restrict__ out,
                             int B, int ngroups) {
    extern __shared__ char smem[];
    const uint32_t sb = (uint32_t)__cvta_generic_to_shared(smem);
    float* xinv_s = (float*)(smem + S_XINV);
    float* cni_s  = (float*)(smem + S_CNI);
    int*   inf_s  = (int*)(smem + S_INF);

    const int tid = threadIdx.x, w = tid >> 5, l = tid & 31;
    const int p = w >> 1;           // pair id: shares a 32-row X slice
    const int h = w & 1;            // A half: classes h*32..h*32+31
    const int barid = p + 1;
    const int Bm1 = B - 1;

    // ---- centroid conversion + norms + inf flags (8 rows per warp, once) ----
    #pragma unroll
    for (int rr = 0; rr < 8; rr++) {
        int r = w * 8 + rr;
        const float4* pa = (const float4*)(A + (size_t)r * 256);
        float4 v0 = pa[l], v1 = pa[32 + l];
        uint32_t c0r, c1r;
        cvt_f16(v0, c0r, c1r);
        sts64(sb + S_A + r * SROW + 8 * l, c0r, c1r);
        cvt_f16(v1, c0r, c1r);
        sts64(sb + S_A + r * SROW + 256 + 8 * l, c0r, c1r);
        float ss = sum8(v0, v1);
        int bad = (fabsf(v0.x) == INFINITY) | (fabsf(v0.y) == INFINITY) |
                  (fabsf(v0.z) == INFINITY) | (fabsf(v0.w) == INFINITY) |
                  (fabsf(v1.x) == INFINITY) | (fabsf(v1.y) == INFINITY) |
                  (fabsf(v1.z) == INFINITY) | (fabsf(v1.w) == INFINITY);
        #pragma unroll
        for (int o = 16; o; o >>= 1) ss += __shfl_xor_sync(FULLM, ss, o);
        unsigned m = __ballot_sync(FULLM, bad);
        if (l == 0) { cni_s[r] = rsqrtf(ss); inf_s[r] = (m != 0); }
    }
    __syncthreads();   // A tile + cni/inf read-only hereafter

    // ---- per-lane ldmatrix fragment offsets ----
    const int t8 = l >> 3;
    const uint32_t frag_off = (uint32_t)(((t8 & 1) * 8 + (l & 7)) * SROW + (t8 >> 1) * 16);
    const uint32_t xslice = sb + S_X + (uint32_t)(p * 32) * SROW;   // pair slice
    const uint32_t xwr    = xslice + (uint32_t)(h * 16) * SROW;     // warp write region
    const uint32_t xf0 = xslice + frag_off;                          // m-block 0
    const uint32_t xf1 = xf0 + 16 * SROW;                            // m-block 1
    const uint32_t af0 = sb + S_A + (uint32_t)(h * 32) * SROW + frag_off;
    const uint32_t af1 = af0 + 16 * SROW;

    const int qr = l >> 2, qc = (l & 3) * 2;

    const int gw = blockIdx.x * 4 + p;          // pair-stream id
    const int gstride = gridDim.x * 4;

    float4 va[4], vb[4], wa[4], wb[4];

    // prologue: LDG waves 0,1 of first group (warp's 16 rows start at +h*16)
    LOADW(va, vb, gw * 32 + h * 16);
    LOADW(wa, wb, gw * 32 + h * 16 + 4);

    for (int grp = gw; grp < ngroups; grp += gstride) {
        const int gb = grp * 32;
        const int lb = gb + h * 16;             // this warp's 16 load rows
        const int ng = grp + gstride;
        const int has_next = (ng < ngroups);
        const int nlb = ng * 32 + h * 16;

        float rw0, rw1, rw2, rw3;
        {
            float4 ta[4], tb[4];                 // third buffer (aliases dead acc)
            LOADW(ta, tb, lb + 8);               // wave2: covered by conv w0+w1
            CONVW(va, vb, 0, rw0);               // convert wave0 (frees va)
            LOADW(va, vb, lb + 12);              // wave3 into va
            CONVW(wa, wb, 4, rw1);               // convert wave1 (frees wa)
            if (has_next) LOADW(wa, wb, nlb + 4); // next WAVE1 -> wa (MMA covers)
            CONVW(ta, tb, 8, rw2);               // convert wave2
            CONVW(va, vb, 12, rw3);              // convert wave3 (frees va)
            if (has_next) LOADW(va, vb, nlb);    // next WAVE0 -> va (MMA covers)
        }
        // publish row rsqrt norms for the pair (partner needs them too)
        if (l < 4) {
            float* xp = xinv_s + p * 32 + h * 16;
            xp[l]      = rsqrtf(rw0);
            xp[4 + l]  = rsqrtf(rw1);
            xp[8 + l]  = rsqrtf(rw2);
            xp[12 + l] = rsqrtf(rw3);
        }
        // pair barrier: 32-row slice + norms complete; partner's ldsm reads
        // of the previous group are done (WAR safe). Other pairs run free.
        asm volatile("bar.sync %0, %1;" :: "r"(barid), "r"(64) : "memory");

        // ---- MMA: 16 k-steps; 32 rows x 32 classes per warp ----
        float acc[2][4][4];
        #pragma unroll
        for (int m = 0; m < 2; m++)
            #pragma unroll
            for (int n = 0; n < 4; n++)
                #pragma unroll
                for (int j = 0; j < 4; j++) acc[m][n][j] = 0.0f;

        #pragma unroll
        for (int s = 0; s < 16; s++) {
            uint32_t x0[4], x1[4], b0[4], b1[4];
            ldsm4(xf0 + s * 32, x0[0], x0[1], x0[2], x0[3]);
            ldsm4(xf1 + s * 32, x1[0], x1[1], x1[2], x1[3]);
            ldsm4(af0 + s * 32, b0[0], b0[1], b0[2], b0[3]);
            ldsm4(af1 + s * 32, b1[0], b1[1], b1[2], b1[3]);
            mma16816(acc[0][0], x0[0], x0[1], x0[2], x0[3], b0[0], b0[2]);
            mma16816(acc[0][1], x0[0], x0[1], x0[2], x0[3], b0[1], b0[3]);
            mma16816(acc[0][2], x0[0], x0[1], x0[2], x0[3], b1[0], b1[2]);
            mma16816(acc[0][3], x0[0], x0[1], x0[2], x0[3], b1[1], b1[3]);
            mma16816(acc[1][0], x1[0], x1[1], x1[2], x1[3], b0[0], b0[2]);
            mma16816(acc[1][1], x1[0], x1[1], x1[2], x1[3], b0[1], b0[3]);
            mma16816(acc[1][2], x1[0], x1[1], x1[2], x1[3], b1[0], b1[2]);
            mma16816(acc[1][3], x1[0], x1[1], x1[2], x1[3], b1[1], b1[3]);
        }

        // ---- epilogue: scale + streaming store (32 rows x 32 classes) ----
        {
            const float* xp = xinv_s + p * 32;
            float xi0 = xp[qr];
            float xi1 = xp[qr + 8];
            float xi2 = xp[qr + 16];
            float xi3 = xp[qr + 24];
            int r0 = gb + qr;
            float* o0 = out + (size_t)r0 * 64;
            float* o1 = o0 + 8 * 64;
            float* o2 = o0 + 16 * 64;
            float* o3 = o0 + 24 * 64;
            bool g0 = (r0 < B), g1 = (r0 + 8 < B), g2 = (r0 + 16 < B), g3 = (r0 + 24 < B);
            #pragma unroll
            for (int n = 0; n < 4; n++) {
                int c0 = h * 32 + n * 8 + qc;
                float2 cn2 = *(const float2*)(cni_s + c0);
                int2   ff  = *(const int2*)(inf_s + c0);
                float2 v0, v1, v2, v3;
                v0.x = ff.x ? 1.0f : acc[0][n][0] * xi0 * cn2.x;
                v0.y = ff.y ? 1.0f : acc[0][n][1] * xi0 * cn2.y;
                v1.x = ff.x ? 1.0f : acc[0][n][2] * xi1 * cn2.x;
                v1.y = ff.y ? 1.0f : acc[0][n][3] * xi1 * cn2.y;
                v2.x = ff.x ? 1.0f : acc[1][n][0] * xi2 * cn2.x;
                v2.y = ff.y ? 1.0f : acc[1][n][1] * xi2 * cn2.y;
                v3.x = ff.x ? 1.0f : acc[1][n][2] * xi3 * cn2.x;
                v3.y = ff.y ? 1.0f : acc[1][n][3] * xi3 * cn2.y;
                if (g0) stg_cs64(o0 + c0, v0);
                if (g1) stg_cs64(o1 + c0, v1);
                if (g2) stg_cs64(o2 + c0, v2);
                if (g3) stg_cs64(o3 + c0, v3);
            }
        }
        // pair barrier: both warps' ldsm/xinv reads of this group done before
        // either overwrites the slice next iteration (WAR).
        asm volatile("bar.sync %0, %1;" :: "r"(barid), "r"(64) : "memory");
    }
}

extern "C" void kernel_launch(void* const* d_in, const int* in_sizes, int n_in,
                              void* d_out, int out_size) {
    const float* X = (const float*)d_in[0];   // inputs [B, 256] fp32
    // d_in[1] = labels (unused)
    const float* A = (const float*)d_in[2];   // class_avgs [64, 256] fp32
    float* out = (float*)d_out;

    int B = in_sizes[0] / 256;
    int ngroups = (B + 31) / 32;

    int dev = 0, nsm = 148;
    cudaGetDevice(&dev);
    cudaDeviceGetAttribute(&nsm, cudaDevAttrMultiProcessorCount, dev);

    int grid = 2 * nsm;             // 2 CTAs/SM, 8 pair-pipelines/SM
    if ((long long)grid * 4 > ngroups) grid = (ngroups + 3) / 4;

    cudaFuncSetAttribute(SimRel_48335561949951_kernel,
                         cudaFuncAttributeMaxDynamicSharedMemorySize, S_TOTAL);

    SimRel_48335561949951_kernel<<<grid, THREADS, S_TOTAL>>>(X, A, out, B, ngroups);
}